// round 1
// baseline (speedup 1.0000x reference)
#include <cuda_runtime.h>
#include <math.h>

#define CORE_DIM 64
#define NB 32
#define TPB 256

// Copy initial utilization into output slot (d_out is poisoned to 0xAA).
__global__ void gc_init_util(const float* __restrict__ util_in,
                             float* __restrict__ util_out) {
    int i = threadIdx.x;
    if (i < NB) util_out[i] = util_in[i];
}

__global__ __launch_bounds__(TPB)
void gc_main(const float* __restrict__ z,
             const float* __restrict__ protos,
             float* __restrict__ act,       // [B, 32]
             float* __restrict__ assign,    // [B]
             float* __restrict__ util,      // [32], pre-initialized
             int B) {
    __shared__ float4 s_proto[NB * (CORE_DIM / 4)];  // [n][d4], 8KB
    __shared__ int s_hist[NB];

    const int tid = threadIdx.x;

    // Stage prototypes (contiguous [n, d] row-major -> float4s)
    #pragma unroll
    for (int i = tid; i < NB * (CORE_DIM / 4); i += TPB)
        s_proto[i] = ((const float4*)protos)[i];
    if (tid < NB) s_hist[tid] = 0;
    __syncthreads();

    const int row = blockIdx.x * TPB + tid;

    if (row < B) {
        float acc[NB];
        #pragma unroll
        for (int n = 0; n < NB; n++) acc[n] = 0.0f;

        const float4* zr = (const float4*)(z + (size_t)row * CORE_DIM);

        #pragma unroll 4
        for (int d4 = 0; d4 < CORE_DIM / 4; d4++) {
            const float4 zv = zr[d4];
            #pragma unroll
            for (int n = 0; n < NB; n++) {
                const float4 p = s_proto[n * (CORE_DIM / 4) + d4];  // broadcast
                acc[n] = fmaf(zv.x, p.x, acc[n]);
                acc[n] = fmaf(zv.y, p.y, acc[n]);
                acc[n] = fmaf(zv.z, p.z, acc[n]);
                acc[n] = fmaf(zv.w, p.w, acc[n]);
            }
        }

        // Exact top-3; strict '>' keeps lower index on ties (matches lax.top_k)
        float v0 = -2.0f, v1 = -2.0f, v2 = -2.0f;
        int   i0 = 0,     i1 = 0,     i2 = 0;
        #pragma unroll
        for (int n = 0; n < NB; n++) {
            const float v = acc[n];
            if (v > v2) {
                if (v > v1) {
                    if (v > v0) {
                        v2 = v1; i2 = i1;
                        v1 = v0; i1 = i0;
                        v0 = v;  i0 = n;
                    } else {
                        v2 = v1; i2 = i1;
                        v1 = v;  i1 = n;
                    }
                } else {
                    v2 = v; i2 = n;
                }
            }
        }

        // Softmax over the 3 survivors at temp 5. Non-top entries are exactly 0
        // (reference: exp((−1e9 − max)/5) underflows to 0 in fp32).
        const float e1 = __expf((v1 - v0) * 0.2f);
        const float e2 = __expf((v2 - v0) * 0.2f);
        const float inv = 1.0f / (1.0f + e1 + e2);

        float* arow = act + (size_t)row * NB;
        const float4 zero4 = make_float4(0.f, 0.f, 0.f, 0.f);
        #pragma unroll
        for (int j = 0; j < NB / 4; j++)
            ((float4*)arow)[j] = zero4;
        arow[i0] = inv;
        arow[i1] = e1 * inv;
        arow[i2] = e2 * inv;

        assign[row] = (float)i0;
        atomicAdd(&s_hist[i0], 1);
    }

    __syncthreads();
    if (tid < NB) {
        const int c = s_hist[tid];
        if (c) atomicAdd(&util[tid], (float)c);
    }
}

extern "C" void kernel_launch(void* const* d_in, const int* in_sizes, int n_in,
                              void* d_out, int out_size) {
    const float* z      = (const float*)d_in[0];
    const float* protos = (const float*)d_in[1];
    const float* u_in   = (const float*)d_in[2];

    const int B = in_sizes[0] / CORE_DIM;

    float* out    = (float*)d_out;
    float* act    = out;                       // B*32
    float* assign = out + (size_t)B * NB;      // B
    float* util   = out + (size_t)B * (NB + 1);// 32

    gc_init_util<<<1, 32>>>(u_in, util);

    const int grid = (B + TPB - 1) / TPB;
    gc_main<<<grid, TPB>>>(z, protos, act, assign, util, B);
}

// round 2
// speedup vs baseline: 1.3193x; 1.3193x over previous
#include <cuda_runtime.h>
#include <math.h>

#define NB 32
#define CD 64
#define TPB 128
#define RPB 256            // rows per block (2 rows per thread)
#define CHUNK_D 32         // d-columns per staging chunk
#define NCHUNK (CD / CHUNK_D)

// ---- packed fp32x2 helpers (Blackwell) ----
__device__ __forceinline__ void fma2(unsigned long long& d,
                                     unsigned long long a,
                                     unsigned long long b) {
    asm("fma.rn.f32x2 %0, %1, %2, %0;" : "+l"(d) : "l"(a), "l"(b));
}
__device__ __forceinline__ unsigned long long splat2(float x) {
    unsigned long long r;
    unsigned int u = __float_as_uint(x);
    asm("mov.b64 %0, {%1, %1};" : "=l"(r) : "r"(u));
    return r;
}
__device__ __forceinline__ void unpack2(unsigned long long v, float& lo, float& hi) {
    unsigned int a, b;
    asm("mov.b64 {%0, %1}, %2;" : "=r"(a), "=r"(b) : "l"(v));
    lo = __uint_as_float(a);
    hi = __uint_as_float(b);
}

__global__ void gc_init_util(const float* __restrict__ u_in,
                             float* __restrict__ u_out) {
    int i = threadIdx.x;
    if (i < NB) u_out[i] = u_in[i];
}

__global__ __launch_bounds__(TPB)
void gc_main(const float* __restrict__ z,
             const float* __restrict__ protos,
             float* __restrict__ act,
             float* __restrict__ assign,
             float* __restrict__ util,
             int B) {
    // z tile: RPB rows x CHUNK_D floats, as float4 with XOR-on-row swizzle
    __shared__ float4      s_z[RPB * (CHUNK_D / 4)];          // 32 KB
    // prototype basin-pairs: [d][16 pairs] as ulonglong2 (2 pairs / 16B)
    __shared__ ulonglong2  s_pp[CD * 8];                      // 8 KB
    __shared__ float4      s_res[RPB];                        // 4 KB (a0,a1,a2,packed idx)
    __shared__ int         s_hist[NB];

    const int tid  = threadIdx.x;
    const int base = blockIdx.x * RPB;

    // ---- build packed prototype table: pair k holds basins (2k, 2k+1) at dim d
    {
        float2* f2 = (float2*)s_pp;    // f2[d*16 + k]
        #pragma unroll
        for (int it = 0; it < (CD * 16) / TPB; it++) {
            int idx = it * TPB + tid;
            int d = idx >> 4;
            int k = idx & 15;
            f2[idx] = make_float2(protos[(2 * k) * CD + d],
                                  protos[(2 * k + 1) * CD + d]);
        }
        if (tid < NB) s_hist[tid] = 0;
    }

    const int r0 = tid;          // local row 0
    const int r1 = tid + TPB;    // local row 1
    const bool ok0 = (base + r0) < B;
    const bool ok1 = (base + r1) < B;

    unsigned long long accA[16], accB[16];
    #pragma unroll
    for (int j = 0; j < 16; j++) { accA[j] = 0ull; accB[j] = 0ull; }

    for (int c = 0; c < NCHUNK; c++) {
        __syncthreads();
        // ---- stage z chunk, fully coalesced LDG.128, swizzled STS
        #pragma unroll
        for (int it = 0; it < (RPB * (CHUNK_D / 4)) / TPB; it++) {
            int idx   = it * TPB + tid;
            int row_l = idx >> 3;          // CHUNK_D/4 == 8
            int d4    = idx & 7;
            int grow  = base + row_l;
            if (grow < B) {
                float4 v = *(const float4*)(z + (size_t)grow * CD + c * CHUNK_D + d4 * 4);
                s_z[row_l * 8 + (d4 ^ (row_l & 7))] = v;
            }
        }
        __syncthreads();

        // ---- compute: 2 rows per thread, FMA2 across basin pairs
        #pragma unroll 1
        for (int d4 = 0; d4 < 8; d4++) {
            float4 a4 = s_z[r0 * 8 + (d4 ^ (r0 & 7))];
            float4 b4 = s_z[r1 * 8 + (d4 ^ (r1 & 7))];
            float ae[4] = {a4.x, a4.y, a4.z, a4.w};
            float be[4] = {b4.x, b4.y, b4.z, b4.w};
            #pragma unroll
            for (int e = 0; e < 4; e++) {
                const int d = c * CHUNK_D + d4 * 4 + e;
                const unsigned long long za = splat2(ae[e]);
                const unsigned long long zb = splat2(be[e]);
                const ulonglong2* pp = &s_pp[d * 8];
                #pragma unroll
                for (int j = 0; j < 8; j++) {
                    ulonglong2 q = pp[j];       // basin pairs 2j, 2j+1 (broadcast LDS.128)
                    fma2(accA[2 * j],     za, q.x);
                    fma2(accA[2 * j + 1], za, q.y);
                    fma2(accB[2 * j],     zb, q.x);
                    fma2(accB[2 * j + 1], zb, q.y);
                }
            }
        }
    }

    // ---- top-3 + softmax per row, stash into s_res
    #pragma unroll
    for (int rsel = 0; rsel < 2; rsel++) {
        const bool ok = rsel ? ok1 : ok0;
        const int  rl = rsel ? r1 : r0;
        if (ok) {
            float v[NB];
            #pragma unroll
            for (int j = 0; j < 16; j++)
                unpack2(rsel ? accB[j] : accA[j], v[2 * j], v[2 * j + 1]);

            float v0 = -2.0f, v1 = -2.0f, v2 = -2.0f;
            int   i0 = 0,     i1 = 0,     i2 = 0;
            #pragma unroll
            for (int n = 0; n < NB; n++) {
                const float x = v[n];
                if (x > v2) {
                    if (x > v1) {
                        if (x > v0) { v2 = v1; i2 = i1; v1 = v0; i1 = i0; v0 = x; i0 = n; }
                        else        { v2 = v1; i2 = i1; v1 = x;  i1 = n; }
                    } else          { v2 = x;  i2 = n; }
                }
            }
            const float e1  = __expf((v1 - v0) * 0.2f);
            const float e2  = __expf((v2 - v0) * 0.2f);
            const float inv = 1.0f / (1.0f + e1 + e2);
            s_res[rl] = make_float4(inv, e1 * inv, e2 * inv,
                                    __int_as_float(i0 | (i1 << 8) | (i2 << 16)));
            atomicAdd(&s_hist[i0], 1);
        }
    }
    __syncthreads();

    // ---- coalesced act stores: one 128B STG per row
    {
        const int warp = tid >> 5;
        const int lane = tid & 31;
        #pragma unroll 4
        for (int r = 0; r < RPB / (TPB / 32); r++) {     // 64 rows per warp
            const int rl   = warp * (RPB / (TPB / 32)) + r;
            const int grow = base + rl;
            if (grow < B) {
                const float4 res = s_res[rl];            // broadcast LDS
                const int pk = __float_as_int(res.w);
                const int i0 = pk & 255, i1 = (pk >> 8) & 255, i2 = (pk >> 16) & 255;
                float val = 0.0f;
                if (lane == i0) val = res.x;
                if (lane == i1) val = res.y;
                if (lane == i2) val = res.z;
                act[(size_t)grow * NB + lane] = val;
            }
        }
    }

    // ---- coalesced assignments
    #pragma unroll
    for (int rl = tid; rl < RPB; rl += TPB) {
        const int grow = base + rl;
        if (grow < B)
            assign[grow] = (float)(__float_as_int(s_res[rl].w) & 255);
    }

    // ---- histogram flush
    if (tid < NB) {
        const int cnt = s_hist[tid];
        if (cnt) atomicAdd(&util[tid], (float)cnt);
    }
}

extern "C" void kernel_launch(void* const* d_in, const int* in_sizes, int n_in,
                              void* d_out, int out_size) {
    const float* z      = (const float*)d_in[0];
    const float* protos = (const float*)d_in[1];
    const float* u_in   = (const float*)d_in[2];

    const int B = in_sizes[0] / CD;

    float* out    = (float*)d_out;
    float* act    = out;
    float* assign = out + (size_t)B * NB;
    float* util   = out + (size_t)B * (NB + 1);

    gc_init_util<<<1, 32>>>(u_in, util);

    const int grid = (B + RPB - 1) / RPB;
    gc_main<<<grid, TPB>>>(z, protos, act, assign, util, B);
}

// round 3
// speedup vs baseline: 1.4118x; 1.0701x over previous
#include <cuda_runtime.h>
#include <math.h>

#define NB 32
#define CD 64
#define TPB 256
#define RPB 512            // rows per block (2 rows per thread)
#define CHUNK_D 32         // d-columns per staging chunk
#define NCHUNK (CD / CHUNK_D)

// ---- packed fp32x2 helpers (Blackwell) ----
__device__ __forceinline__ void fma2(unsigned long long& d,
                                     unsigned long long a,
                                     unsigned long long b) {
    asm("fma.rn.f32x2 %0, %1, %2, %0;" : "+l"(d) : "l"(a), "l"(b));
}
__device__ __forceinline__ unsigned long long splat2(float x) {
    unsigned long long r;
    unsigned int u = __float_as_uint(x);
    asm("mov.b64 %0, {%1, %1};" : "=l"(r) : "r"(u));
    return r;
}
__device__ __forceinline__ void unpack2(unsigned long long v, float& lo, float& hi) {
    unsigned int a, b;
    asm("mov.b64 {%0, %1}, %2;" : "=r"(a), "=r"(b) : "l"(v));
    lo = __uint_as_float(a);
    hi = __uint_as_float(b);
}

__global__ void gc_init_util(const float* __restrict__ u_in,
                             float* __restrict__ u_out) {
    int i = threadIdx.x;
    if (i < NB) u_out[i] = u_in[i];
}

__global__ __launch_bounds__(TPB, 2)
void gc_main(const float* __restrict__ z,
             const float* __restrict__ protos,
             float* __restrict__ act,
             float* __restrict__ assign,
             float* __restrict__ util,
             int B) {
    // z tile: RPB rows x CHUNK_D floats, float4 with XOR-on-row swizzle (64 KB)
    __shared__ float4      s_z[RPB * (CHUNK_D / 4)];
    // prototype basin-pairs: [d][16 pairs] as ulonglong2 (8 KB)
    __shared__ ulonglong2  s_pp[CD * 8];
    __shared__ float4      s_res[RPB];                        // 8 KB
    __shared__ int         s_hist[NB];

    const int tid  = threadIdx.x;
    const int base = blockIdx.x * RPB;

    // ---- build packed prototype table: pair k holds basins (2k, 2k+1) at dim d
    {
        float2* f2 = (float2*)s_pp;    // f2[d*16 + k]
        #pragma unroll
        for (int it = 0; it < (CD * 16) / TPB; it++) {
            int idx = it * TPB + tid;
            int d = idx >> 4;
            int k = idx & 15;
            f2[idx] = make_float2(protos[(2 * k) * CD + d],
                                  protos[(2 * k + 1) * CD + d]);
        }
        if (tid < NB) s_hist[tid] = 0;
    }

    const int r0 = tid;          // local row 0
    const int r1 = tid + TPB;    // local row 1
    const bool ok0 = (base + r0) < B;
    const bool ok1 = (base + r1) < B;

    unsigned long long accA[16], accB[16];
    #pragma unroll
    for (int j = 0; j < 16; j++) { accA[j] = 0ull; accB[j] = 0ull; }

    for (int c = 0; c < NCHUNK; c++) {
        __syncthreads();
        // ---- stage z chunk, fully coalesced LDG.128, swizzled STS
        #pragma unroll
        for (int it = 0; it < (RPB * (CHUNK_D / 4)) / TPB; it++) {
            int idx   = it * TPB + tid;
            int row_l = idx >> 3;          // CHUNK_D/4 == 8
            int d4    = idx & 7;
            int grow  = base + row_l;
            if (grow < B) {
                float4 v = *(const float4*)(z + (size_t)grow * CD + c * CHUNK_D + d4 * 4);
                s_z[row_l * 8 + (d4 ^ (row_l & 7))] = v;
            }
        }
        __syncthreads();

        // ---- compute: 2 rows per thread, FMA2 across basin pairs
        #pragma unroll 2
        for (int d4 = 0; d4 < 8; d4++) {
            float4 a4 = s_z[r0 * 8 + (d4 ^ (r0 & 7))];
            float4 b4 = s_z[r1 * 8 + (d4 ^ (r1 & 7))];
            float ae[4] = {a4.x, a4.y, a4.z, a4.w};
            float be[4] = {b4.x, b4.y, b4.z, b4.w};
            #pragma unroll
            for (int e = 0; e < 4; e++) {
                const int d = c * CHUNK_D + d4 * 4 + e;
                const unsigned long long za = splat2(ae[e]);
                const unsigned long long zb = splat2(be[e]);
                const ulonglong2* pp = &s_pp[d * 8];
                #pragma unroll
                for (int j = 0; j < 8; j++) {
                    ulonglong2 q = pp[j];       // basin pairs 2j, 2j+1 (broadcast LDS.128)
                    fma2(accA[2 * j],     za, q.x);
                    fma2(accA[2 * j + 1], za, q.y);
                    fma2(accB[2 * j],     zb, q.x);
                    fma2(accB[2 * j + 1], zb, q.y);
                }
            }
        }
    }

    // ---- top-3 + softmax per row, stash into s_res
    #pragma unroll
    for (int rsel = 0; rsel < 2; rsel++) {
        const bool ok = rsel ? ok1 : ok0;
        const int  rl = rsel ? r1 : r0;
        if (ok) {
            float v[NB];
            #pragma unroll
            for (int j = 0; j < 16; j++)
                unpack2(rsel ? accB[j] : accA[j], v[2 * j], v[2 * j + 1]);

            float v0 = -2.0f, v1 = -2.0f, v2 = -2.0f;
            int   i0 = 0,     i1 = 0,     i2 = 0;
            #pragma unroll
            for (int n = 0; n < NB; n++) {
                const float x = v[n];
                if (x > v2) {
                    if (x > v1) {
                        if (x > v0) { v2 = v1; i2 = i1; v1 = v0; i1 = i0; v0 = x; i0 = n; }
                        else        { v2 = v1; i2 = i1; v1 = x;  i1 = n; }
                    } else          { v2 = x;  i2 = n; }
                }
            }
            const float e1  = __expf((v1 - v0) * 0.2f);
            const float e2  = __expf((v2 - v0) * 0.2f);
            const float inv = 1.0f / (1.0f + e1 + e2);
            s_res[rl] = make_float4(inv, e1 * inv, e2 * inv,
                                    __int_as_float(i0 | (i1 << 8) | (i2 << 16)));
            atomicAdd(&s_hist[i0], 1);
        }
    }
    __syncthreads();

    // ---- coalesced act stores: one 128B STG per row
    {
        const int warp = tid >> 5;
        const int lane = tid & 31;
        #pragma unroll 4
        for (int r = 0; r < RPB / (TPB / 32); r++) {     // 64 rows per warp
            const int rl   = warp * (RPB / (TPB / 32)) + r;
            const int grow = base + rl;
            if (grow < B) {
                const float4 res = s_res[rl];            // broadcast LDS
                const int pk = __float_as_int(res.w);
                const int i0 = pk & 255, i1 = (pk >> 8) & 255, i2 = (pk >> 16) & 255;
                float val = 0.0f;
                if (lane == i0) val = res.x;
                if (lane == i1) val = res.y;
                if (lane == i2) val = res.z;
                act[(size_t)grow * NB + lane] = val;
            }
        }
    }

    // ---- coalesced assignments
    #pragma unroll
    for (int rl = tid; rl < RPB; rl += TPB) {
        const int grow = base + rl;
        if (grow < B)
            assign[grow] = (float)(__float_as_int(s_res[rl].w) & 255);
    }

    // ---- histogram flush
    if (tid < NB) {
        const int cnt = s_hist[tid];
        if (cnt) atomicAdd(&util[tid], (float)cnt);
    }
}

extern "C" void kernel_launch(void* const* d_in, const int* in_sizes, int n_in,
                              void* d_out, int out_size) {
    const float* z      = (const float*)d_in[0];
    const float* protos = (const float*)d_in[1];
    const float* u_in   = (const float*)d_in[2];

    const int B = in_sizes[0] / CD;

    float* out    = (float*)d_out;
    float* act    = out;
    float* assign = out + (size_t)B * NB;
    float* util   = out + (size_t)B * (NB + 1);

    gc_init_util<<<1, 32>>>(u_in, util);

    const int grid = (B + RPB - 1) / RPB;
    gc_main<<<grid, TPB>>>(z, protos, act, assign, util, B);
}